// round 4
// baseline (speedup 1.0000x reference)
#include <cuda_runtime.h>

#define P_ 16
#define B_ 4
#define C_ 256
#define N_ 256
#define TJ 64
#define QP 260
#define PP 260
#define VP 17

// 16 MB scratch for corr[p,b,i,d] (d contiguous)
__device__ float g_corr[(size_t)P_ * B_ * N_ * C_];

// ---------------------------------------------------------------------------
// Kernel 1: corr[p,b,i,d] = sum_c tf[p,b,c,i] * We[d,c]
// grid (16, 64): x -> (i-tile, d-tile), y -> p*B+b. 64x64 output tile per CTA.
// ---------------------------------------------------------------------------
__global__ void __launch_bounds__(256) corr_kernel(const float* __restrict__ temp,
                                                   const float* __restrict__ We) {
    __shared__ float sX[16][64];   // [c-chunk][i]
    __shared__ float sW[64][17];   // [d][c-chunk]
    const int t = threadIdx.x;
    const int tx = t & 15, ty = t >> 4;
    const int ti = blockIdx.x & 3, td = blockIdx.x >> 2;
    const int pb = blockIdx.y;
    const float* tf = temp + (size_t)pb * C_ * N_;
    const int i0 = ti * 64, d0 = td * 64;

    float acc[4][4];
#pragma unroll
    for (int u = 0; u < 4; u++)
#pragma unroll
        for (int v = 0; v < 4; v++) acc[u][v] = 0.f;

#pragma unroll 1
    for (int kc = 0; kc < 16; kc++) {
        __syncthreads();
#pragma unroll
        for (int r = 0; r < 4; r++) {
            int e = t + r * 256;
            sX[e >> 6][e & 63] = tf[(kc * 16 + (e >> 6)) * N_ + i0 + (e & 63)];
        }
#pragma unroll
        for (int r = 0; r < 4; r++) {
            int e = t + r * 256;
            sW[e >> 4][e & 15] = We[(size_t)(d0 + (e >> 4)) * C_ + kc * 16 + (e & 15)];
        }
        __syncthreads();
#pragma unroll
        for (int cc = 0; cc < 16; cc++) {
            float a[4], bb[4];
#pragma unroll
            for (int u = 0; u < 4; u++) a[u] = sX[cc][tx * 4 + u];
#pragma unroll
            for (int v = 0; v < 4; v++) bb[v] = sW[ty * 4 + v][cc];
#pragma unroll
            for (int u = 0; u < 4; u++)
#pragma unroll
                for (int v = 0; v < 4; v++) acc[u][v] += a[u] * bb[v];
        }
    }
    float* cr = g_corr + (size_t)pb * N_ * C_;
#pragma unroll
    for (int u = 0; u < 4; u++) {
        int i = i0 + tx * 4 + u;
        float4 w = make_float4(acc[u][0], acc[u][1], acc[u][2], acc[u][3]);
        *(float4*)&cr[(size_t)i * C_ + d0 + ty * 4] = w;
    }
}

__device__ __forceinline__ float inv_patch(const void* p) {
    if (p == nullptr) return 1.f / 16.f;
    int iv = *(const int*)p;
    if (iv >= 1 && iv <= 65536) return 1.f / (float)iv;
    float fv = __int_as_float(iv);
    if (fv >= 0.5f && fv <= 65536.f) return 1.f / fv;
    return 1.f / 16.f;
}

// ---------------------------------------------------------------------------
// Kernel 2: fused per (p, b, j-tile of 64). Loops q = 0..15:
//   A[j,i]   = sum_d corr[p,b,j,d] * tf[q,b,d,i]     (GEMM1, 64x256x256)
//   P[j,:]   = softmax_i(A[j,:])
//   att[c,j] = sum_i tf[q,b,c,i] * P[j,i]            (GEMM2, 256x64x256)
//   mask[j]  = sigmoid(sum_c att[c,j] * Wg[c])
//   out[c,j] += att[c,j] * mask[j]
// Finally out *= 1/patch_num.
// ---------------------------------------------------------------------------
__global__ void __launch_bounds__(256, 1)
fused_kernel(const float* __restrict__ temp,
             const float* __restrict__ Wg,
             const void* __restrict__ pnp,
             float* __restrict__ out) {
    extern __shared__ float sm[];
    float* sQ    = sm;                  // [TJ][QP] corr rows (j0..j0+63, all d)
    float* sP    = sQ + TJ * QP;        // [TJ][PP] A / P; reused as attS[256][64]
    float* sK    = sP + TJ * PP;        // [16][256]  tf d-chunk for GEMM1
    float* sV    = sK + 16 * 256;       // [256][VP]  tf i-chunk for GEMM2
    float* sWg   = sV + 256 * VP;       // [256]
    float* sMask = sWg + 256;           // [64]

    const int t = threadIdx.x;
    const int bid = blockIdx.x;
    const int jt = bid & 3;
    const int b  = (bid >> 2) & 3;
    const int p  = bid >> 4;
    const int j0 = jt * TJ;

    const int tx1 = t & 15, ty1 = t >> 4;   // GEMM1: 4j x 16i micro
    const int tx2 = t & 3,  ty2 = t >> 2;   // GEMM2: 4c x 16j micro (j interleaved)
    const int c0 = ty2 * 4;

    sWg[t] = Wg[t];

    // load Q (corr rows) once
    {
        const float* cr = g_corr + ((size_t)(p * B_ + b) * N_ + j0) * C_;
#pragma unroll 4
        for (int r = 0; r < TJ; r++)
            sQ[r * QP + t] = cr[(size_t)r * C_ + t];
    }

    float outAcc[4][16];
#pragma unroll
    for (int r = 0; r < 4; r++)
#pragma unroll
        for (int k = 0; k < 16; k++) outAcc[r][k] = 0.f;

#pragma unroll 1
    for (int q = 0; q < P_; q++) {
        const float* tfq = temp + (size_t)(q * B_ + b) * C_ * N_;

        // ---- GEMM1: A[j,i] over d ----
        float acc1[4][16];
#pragma unroll
        for (int r = 0; r < 4; r++)
#pragma unroll
            for (int k = 0; k < 16; k++) acc1[r][k] = 0.f;

#pragma unroll 1
        for (int kc = 0; kc < 16; kc++) {
            __syncthreads();
#pragma unroll
            for (int r = 0; r < 16; r++)
                sK[r * 256 + t] = tfq[(size_t)(kc * 16 + r) * N_ + t];
            __syncthreads();
#pragma unroll
            for (int dd = 0; dd < 16; dd++) {
                float a[4];
#pragma unroll
                for (int rr = 0; rr < 4; rr++)
                    a[rr] = sQ[(ty1 * 4 + rr) * QP + kc * 16 + dd];
#pragma unroll
                for (int v = 0; v < 4; v++) {
                    float4 b4 = *(const float4*)&sK[dd * 256 + v * 64 + tx1 * 4];
                    float bv[4] = {b4.x, b4.y, b4.z, b4.w};
#pragma unroll
                    for (int rr = 0; rr < 4; rr++)
#pragma unroll
                        for (int u = 0; u < 4; u++)
                            acc1[rr][v * 4 + u] += a[rr] * bv[u];
                }
            }
        }
        __syncthreads();
        // write A into sP[j][i]
#pragma unroll
        for (int rr = 0; rr < 4; rr++) {
            int j = ty1 * 4 + rr;
#pragma unroll
            for (int v = 0; v < 4; v++) {
                float4 w = make_float4(acc1[rr][v * 4 + 0], acc1[rr][v * 4 + 1],
                                       acc1[rr][v * 4 + 2], acc1[rr][v * 4 + 3]);
                *(float4*)&sP[j * PP + v * 64 + tx1 * 4] = w;
            }
        }
        __syncthreads();

        // ---- softmax rows over i ----
        {
            const int w = t >> 5, l = t & 31;
#pragma unroll 1
            for (int rr = 0; rr < 8; rr++) {
                int j = w * 8 + rr;
                float v[8];
#pragma unroll
                for (int m = 0; m < 8; m++) v[m] = sP[j * PP + l + m * 32];
                float mx = v[0];
#pragma unroll
                for (int m = 1; m < 8; m++) mx = fmaxf(mx, v[m]);
#pragma unroll
                for (int o = 16; o > 0; o >>= 1)
                    mx = fmaxf(mx, __shfl_xor_sync(0xffffffffu, mx, o));
                float s = 0.f;
#pragma unroll
                for (int m = 0; m < 8; m++) { v[m] = __expf(v[m] - mx); s += v[m]; }
#pragma unroll
                for (int o = 16; o > 0; o >>= 1)
                    s += __shfl_xor_sync(0xffffffffu, s, o);
                float inv = 1.f / s;
#pragma unroll
                for (int m = 0; m < 8; m++) sP[j * PP + l + m * 32] = v[m] * inv;
            }
        }
        __syncthreads();

        // ---- GEMM2: att[c,j] over i ----
        float acc2[4][16];
#pragma unroll
        for (int r = 0; r < 4; r++)
#pragma unroll
            for (int k = 0; k < 16; k++) acc2[r][k] = 0.f;

#pragma unroll 1
        for (int kc = 0; kc < 16; kc++) {
#pragma unroll
            for (int r = 0; r < 16; r++) {
                int e = t + r * 256;
                int c = e >> 4, ii = e & 15;
                sV[c * VP + ii] = tfq[(size_t)c * N_ + kc * 16 + ii];
            }
            __syncthreads();
#pragma unroll
            for (int ii = 0; ii < 16; ii++) {
                float vv[4];
#pragma unroll
                for (int r = 0; r < 4; r++) vv[r] = sV[(c0 + r) * VP + ii];
#pragma unroll
                for (int k = 0; k < 16; k++) {
                    float pk = sP[(tx2 + 4 * k) * PP + kc * 16 + ii];
#pragma unroll
                    for (int r = 0; r < 4; r++) acc2[r][k] += vv[r] * pk;
                }
            }
            __syncthreads();
        }

        // ---- stage att into smem (reuse sP) for gate reduction ----
#pragma unroll
        for (int r = 0; r < 4; r++)
#pragma unroll
            for (int k = 0; k < 16; k++)
                sP[(c0 + r) * 64 + (tx2 + 4 * k)] = acc2[r][k];
        __syncthreads();

        // ---- mask[j] = sigmoid(sum_c att[c,j]*Wg[c]) ----
        if (t < 64) {
            float s = 0.f;
#pragma unroll 8
            for (int c = 0; c < 256; c++) s += sP[c * 64 + t] * sWg[c];
            sMask[t] = 1.f / (1.f + __expf(-s));
        }
        __syncthreads();

        // ---- accumulate gated att over q ----
#pragma unroll
        for (int k = 0; k < 16; k++) {
            float m = sMask[tx2 + 4 * k];
#pragma unroll
            for (int r = 0; r < 4; r++) outAcc[r][k] += acc2[r][k] * m;
        }
    }

    // ---- write out ----
    const float invp = inv_patch(pnp);
    float* ob = out + (size_t)(p * B_ + b) * C_ * N_;
#pragma unroll
    for (int r = 0; r < 4; r++) {
        int c = c0 + r;
#pragma unroll
        for (int k = 0; k < 16; k++)
            ob[(size_t)c * N_ + j0 + tx2 + 4 * k] = outAcc[r][k] * invp;
    }
}

// ---------------------------------------------------------------------------
extern "C" void kernel_launch(void* const* d_in, const int* in_sizes, int n_in,
                              void* d_out, int out_size) {
    const float* temp = (const float*)d_in[0];
    const float* We   = (const float*)d_in[1];
    const float* Wg   = (const float*)d_in[2];
    const void*  pn   = (n_in > 3) ? d_in[3] : nullptr;
    float* out = (float*)d_out;

    corr_kernel<<<dim3(16, 64), 256>>>(temp, We);

    const size_t smem = (size_t)(TJ * QP + TJ * PP + 16 * 256 + 256 * VP + 256 + 64) * sizeof(float);
    cudaFuncSetAttribute(fused_kernel, cudaFuncAttributeMaxDynamicSharedMemorySize, (int)smem);
    fused_kernel<<<256, 256, smem>>>(temp, Wg, pn, out);
}

// round 7
// speedup vs baseline: 2.0762x; 2.0762x over previous
#include <cuda_runtime.h>
#include <cuda_bf16.h>
#include <cstdint>

#define P_ 16
#define B_ 4
#define C_ 256
#define N_ 256
#define PB_ 64

typedef __nv_bfloat16 bf16;

// ---------------- gmem scratch (static __device__, no allocs) ----------------
__device__ __align__(16) float g_corr[(size_t)PB_ * N_ * C_];   // corr[pb][j][d]
__device__ __align__(16) bf16  g_corr_h[(size_t)PB_ * N_ * C_];
__device__ __align__(16) bf16  g_corr_l[(size_t)PB_ * N_ * C_];
__device__ __align__(16) bf16  g_tf_h[(size_t)PB_ * C_ * N_];   // temp split [pb][c][i]
__device__ __align__(16) bf16  g_tf_l[(size_t)PB_ * C_ * N_];
__device__ __align__(16) bf16  g_tfT_h[(size_t)PB_ * N_ * C_];  // temp^T split [pb][i][c]
__device__ __align__(16) bf16  g_tfT_l[(size_t)PB_ * N_ * C_];
__device__ __align__(16) float g_wtf[(size_t)PB_ * N_];         // wtf[pb][i]

// ---------------- helpers ----------------
__device__ __forceinline__ uint32_t smem_u32(const void* p) {
    uint32_t a;
    asm("{ .reg .u64 t; cvta.to.shared.u64 t, %1; cvt.u32.u64 %0, t; }" : "=r"(a) : "l"(p));
    return a;
}
__device__ __forceinline__ void ldm_x4(uint32_t& r0, uint32_t& r1, uint32_t& r2,
                                       uint32_t& r3, uint32_t a) {
    asm volatile("ldmatrix.sync.aligned.m8n8.x4.shared.b16 {%0,%1,%2,%3}, [%4];"
                 : "=r"(r0), "=r"(r1), "=r"(r2), "=r"(r3) : "r"(a));
}
__device__ __forceinline__ void mma16816(float* c, const uint32_t* a,
                                         uint32_t b0, uint32_t b1) {
    asm volatile("mma.sync.aligned.m16n8k16.row.col.f32.bf16.bf16.f32 "
                 "{%0,%1,%2,%3}, {%4,%5,%6,%7}, {%8,%9}, {%0,%1,%2,%3};"
                 : "+f"(c[0]), "+f"(c[1]), "+f"(c[2]), "+f"(c[3])
                 : "r"(a[0]), "r"(a[1]), "r"(a[2]), "r"(a[3]), "r"(b0), "r"(b1));
}
// pack two floats to bf16x2: lo -> lower 16 bits, hi -> upper 16 bits
__device__ __forceinline__ uint32_t pack_bf(float lo, float hi) {
    uint32_t r;
    asm("cvt.rn.bf16x2.f32 %0, %1, %2;" : "=r"(r) : "f"(hi), "f"(lo));
    return r;
}
__device__ __forceinline__ uint32_t pack2_bf16(bf16 lo, bf16 hi) {
    return ((uint32_t)__bfloat16_as_ushort(hi) << 16) | (uint32_t)__bfloat16_as_ushort(lo);
}

__device__ __forceinline__ float inv_patch(const void* p) {
    if (p == nullptr) return 1.f / 16.f;
    int iv = *(const int*)p;
    if (iv >= 1 && iv <= 65536) return 1.f / (float)iv;
    float fv = __int_as_float(iv);
    if (fv >= 0.5f && fv <= 65536.f) return 1.f / fv;
    return 1.f / 16.f;
}

// stage one 128-byte row into SW128-swizzled smem (row r)
__device__ __forceinline__ void stage_row128(const uint4* __restrict__ src,
                                             char* dstBase, int r) {
    const uint32_t sw = (uint32_t)((r & 7) << 4);
    char* row = dstBase + r * 128;
#pragma unroll
    for (int v = 0; v < 8; v++) {
        uint4 x = src[v];
        *(uint4*)(row + ((uint32_t)(v * 16) ^ sw)) = x;
    }
}

// ---------------------------------------------------------------------------
// Prep 1: corr[pb][j][d] = sum_c temp[pb][c][j] * We[d][c]   (fp32, verified R1)
// ---------------------------------------------------------------------------
__global__ void __launch_bounds__(256) corr_kernel(const float* __restrict__ temp,
                                                   const float* __restrict__ We) {
    __shared__ float sX[16][64];
    __shared__ float sW[64][17];
    const int t = threadIdx.x;
    const int tx = t & 15, ty = t >> 4;
    const int ti = blockIdx.x & 3, td = blockIdx.x >> 2;
    const int pb = blockIdx.y;
    const float* tf = temp + (size_t)pb * C_ * N_;
    const int i0 = ti * 64, d0 = td * 64;

    float acc[4][4];
#pragma unroll
    for (int u = 0; u < 4; u++)
#pragma unroll
        for (int v = 0; v < 4; v++) acc[u][v] = 0.f;

#pragma unroll 1
    for (int kc = 0; kc < 16; kc++) {
        __syncthreads();
#pragma unroll
        for (int r = 0; r < 4; r++) {
            int e = t + r * 256;
            sX[e >> 6][e & 63] = tf[(kc * 16 + (e >> 6)) * N_ + i0 + (e & 63)];
        }
#pragma unroll
        for (int r = 0; r < 4; r++) {
            int e = t + r * 256;
            sW[e >> 4][e & 15] = We[(size_t)(d0 + (e >> 4)) * C_ + kc * 16 + (e & 15)];
        }
        __syncthreads();
#pragma unroll
        for (int cc = 0; cc < 16; cc++) {
            float a[4], bb[4];
#pragma unroll
            for (int u = 0; u < 4; u++) a[u] = sX[cc][tx * 4 + u];
#pragma unroll
            for (int v = 0; v < 4; v++) bb[v] = sW[ty * 4 + v][cc];
#pragma unroll
            for (int u = 0; u < 4; u++)
#pragma unroll
                for (int v = 0; v < 4; v++) acc[u][v] += a[u] * bb[v];
        }
    }
    float* cr = g_corr + (size_t)pb * N_ * C_;
#pragma unroll
    for (int u = 0; u < 4; u++) {
        int i = i0 + tx * 4 + u;
        float4 w4 = make_float4(acc[u][0], acc[u][1], acc[u][2], acc[u][3]);
        *(float4*)&cr[(size_t)i * C_ + d0 + ty * 4] = w4;
    }
}

// ---------------------------------------------------------------------------
// Prep 2a/2b: elementwise bf16 hi/lo splits (reference globals directly)
// ---------------------------------------------------------------------------
__device__ __forceinline__ void split4(const float4 x, uint2& uh, uint2& ul) {
    bf16 h0 = __float2bfloat16(x.x), h1 = __float2bfloat16(x.y);
    bf16 h2 = __float2bfloat16(x.z), h3 = __float2bfloat16(x.w);
    bf16 l0 = __float2bfloat16(x.x - __bfloat162float(h0));
    bf16 l1 = __float2bfloat16(x.y - __bfloat162float(h1));
    bf16 l2 = __float2bfloat16(x.z - __bfloat162float(h2));
    bf16 l3 = __float2bfloat16(x.w - __bfloat162float(h3));
    uh = make_uint2(pack2_bf16(h0, h1), pack2_bf16(h2, h3));
    ul = make_uint2(pack2_bf16(l0, l1), pack2_bf16(l2, l3));
}
__global__ void __launch_bounds__(256) split_corr() {
    size_t i = (size_t)blockIdx.x * 256 + threadIdx.x;
    float4 x = ((const float4*)g_corr)[i];
    uint2 uh, ul;
    split4(x, uh, ul);
    ((uint2*)g_corr_h)[i] = uh;
    ((uint2*)g_corr_l)[i] = ul;
}
__global__ void __launch_bounds__(256) split_tf(const float* __restrict__ temp) {
    size_t i = (size_t)blockIdx.x * 256 + threadIdx.x;
    float4 x = ((const float4*)temp)[i];
    uint2 uh, ul;
    split4(x, uh, ul);
    ((uint2*)g_tf_h)[i] = uh;
    ((uint2*)g_tf_l)[i] = ul;
}

// ---------------------------------------------------------------------------
// Prep 3: transpose + split: tfT[pb][i][c] = temp[pb][c][i]
// ---------------------------------------------------------------------------
__global__ void __launch_bounds__(256) transpose_split(const float* __restrict__ temp) {
    __shared__ float tile[32][33];
    const int pb = blockIdx.z;
    const int i0 = blockIdx.x * 32, c0 = blockIdx.y * 32;
    const int tx = threadIdx.x & 31, ty = threadIdx.x >> 5;
    const float* src = temp + (size_t)pb * C_ * N_;
#pragma unroll
    for (int k = 0; k < 4; k++) {
        int c = c0 + ty + k * 8;
        tile[ty + k * 8][tx] = src[(size_t)c * N_ + i0 + tx];
    }
    __syncthreads();
#pragma unroll
    for (int k = 0; k < 4; k++) {
        int i = i0 + ty + k * 8;
        float x = tile[tx][ty + k * 8];
        size_t o = (size_t)pb * N_ * C_ + (size_t)i * C_ + c0 + tx;
        bf16 hh = __float2bfloat16(x);
        g_tfT_h[o] = hh;
        g_tfT_l[o] = __float2bfloat16(x - __bfloat162float(hh));
    }
}

// ---------------------------------------------------------------------------
// Prep 4: wtf[pb][i] = sum_c Wg[c] * temp[pb][c][i]
// ---------------------------------------------------------------------------
__global__ void __launch_bounds__(256) wtf_kernel(const float* __restrict__ temp,
                                                  const float* __restrict__ Wg) {
    __shared__ float sWg[256];
    const int pb = blockIdx.x, i = threadIdx.x;
    sWg[i] = Wg[i];
    __syncthreads();
    const float* src = temp + (size_t)pb * C_ * N_;
    float s = 0.f;
#pragma unroll 8
    for (int c = 0; c < 256; c++) s += src[(size_t)c * N_ + i] * sWg[c];
    g_wtf[(size_t)pb * N_ + i] = s;
}

// ---------------------------------------------------------------------------
// Fused mma.sync kernel. 128 CTAs = (pb 64) x (j-tile 2 of 128). 256 threads.
// SMEM layout (bytes):
//   [0,32K)    SB_H : B-operand hi, 256 rows x 128B (SW128)
//   [32K,64K)  SB_L : B-operand lo
//   [64K,128K) PH   : P hi, 4 chunks x (128 rows x 128B); chunks 0-1 alias
//                     CORR_H/CORR_L staging during GEMM1
//   [128K,192K)PL   : P lo, 4 chunks
//   [192K,..)  sWtf : 256 floats
// ---------------------------------------------------------------------------
#define SB_H 0
#define SB_L 32768
#define PH 65536
#define PL 131072
#define CORR_H 65536
#define CORR_L 81920
#define SWTF 196608
#define SMEM_TOTAL (196608 + 1024)

__global__ void __launch_bounds__(256, 1)
fused_mma(const void* __restrict__ pnp, float* __restrict__ out) {
    extern __shared__ char smd[];
    const uint32_t sb = smem_u32(smd);
    float* sWtf = (float*)(smd + SWTF);

    const int t = threadIdx.x;
    const int w = t >> 5, lane = t & 31;
    const int jt = blockIdx.x & 1;
    const int pb = blockIdx.x >> 1;
    const int b = pb & 3;
    const int j0 = jt * 128;

    const float invp = inv_patch(pnp);

    // ldmatrix lane-address components (constant per thread)
    const int a_row_off = ((lane >> 3) & 1) * 8 + (lane & 7);   // A-frag row offset
    const int a_col_off = ((lane >> 4) & 1) * 16;               // A-frag col byte offset
    const int b_row_off = ((lane >> 4) & 1) * 8 + (lane & 7);   // B-frag row offset
    const int b_col_off = ((lane >> 3) & 1) * 16;               // B-frag col byte offset

#pragma unroll 1
    for (int q = 0; q < P_; q++) {
        const int qb = q * B_ + b;

        // ==================== GEMM1: logits[128j x 256i] =====================
        float acc[32][4];
#pragma unroll
        for (int n = 0; n < 32; n++)
#pragma unroll
            for (int x = 0; x < 4; x++) acc[n][x] = 0.f;

#pragma unroll 1
        for (int kc = 0; kc < 4; kc++) {
            __syncthreads();
            if (kc == 0) sWtf[t] = g_wtf[(size_t)qb * N_ + t];
            {   // stage B: tfT rows 0..255, d-chunk kc (hi + lo)
                const size_t o = (size_t)qb * 65536 + (size_t)t * 256 + kc * 64;
                stage_row128((const uint4*)(g_tfT_h + o), smd + SB_H, t);
                stage_row128((const uint4*)(g_tfT_l + o), smd + SB_L, t);
            }
            {   // stage A: corr rows j0..j0+127, d-chunk kc
                if (t < 128) {
                    const size_t o = (size_t)pb * 65536 + (size_t)(j0 + t) * 256 + kc * 64;
                    stage_row128((const uint4*)(g_corr_h + o), smd + CORR_H, t);
                } else {
                    const size_t o = (size_t)pb * 65536 + (size_t)(j0 + t - 128) * 256 + kc * 64;
                    stage_row128((const uint4*)(g_corr_l + o), smd + CORR_L, t - 128);
                }
            }
            __syncthreads();
#pragma unroll
            for (int k16 = 0; k16 < 4; k16++) {
                uint32_t ah[4], al[4];
                {
                    const int ar = 16 * w + a_row_off;
                    const uint32_t ad = sb + CORR_H + ar * 128 +
                        ((uint32_t)(k16 * 32 + a_col_off) ^ ((ar & 7) << 4));
                    ldm_x4(ah[0], ah[1], ah[2], ah[3], ad);
                    ldm_x4(al[0], al[1], al[2], al[3], ad + 16384);
                }
                const uint32_t bc = (uint32_t)(k16 * 32 + b_col_off);
#pragma unroll
                for (int np = 0; np < 16; np++) {
                    const int br = np * 16 + b_row_off;
                    const uint32_t bd = sb + SB_H + br * 128 + (bc ^ ((br & 7) << 4));
                    uint32_t bh[4], bl[4];
                    ldm_x4(bh[0], bh[1], bh[2], bh[3], bd);
                    ldm_x4(bl[0], bl[1], bl[2], bl[3], bd + 32768);
                    mma16816(acc[2 * np],     ah, bh[0], bh[1]);
                    mma16816(acc[2 * np + 1], ah, bh[2], bh[3]);
                    mma16816(acc[2 * np],     ah, bl[0], bl[1]);
                    mma16816(acc[2 * np + 1], ah, bl[2], bl[3]);
                    mma16816(acc[2 * np],     al, bh[0], bh[1]);
                    mma16816(acc[2 * np + 1], al, bh[2], bh[3]);
                }
            }
        }
        __syncthreads();   // all GEMM1 smem reads done before P overwrites CORR area

        // ============ softmax (unnorm, shift 40) + gate fold + P write =======
        {
            float s1 = 0.f, g1 = 0.f, s2 = 0.f, g2 = 0.f;
#pragma unroll
            for (int nt = 0; nt < 32; nt++) {
                const int col = nt * 8 + (lane & 3) * 2;
                float2 wv = *(float2*)&sWtf[col];
                float e0 = __expf(acc[nt][0] - 40.f);
                float e1 = __expf(acc[nt][1] - 40.f);
                float e2 = __expf(acc[nt][2] - 40.f);
                float e3 = __expf(acc[nt][3] - 40.f);
                acc[nt][0] = e0; acc[nt][1] = e1; acc[nt][2] = e2; acc[nt][3] = e3;
                s1 += e0 + e1; g1 += e0 * wv.x + e1 * wv.y;
                s2 += e2 + e3; g2 += e2 * wv.x + e3 * wv.y;
            }
#pragma unroll
            for (int o = 1; o <= 2; o <<= 1) {
                s1 += __shfl_xor_sync(0xffffffffu, s1, o);
                g1 += __shfl_xor_sync(0xffffffffu, g1, o);
                s2 += __shfl_xor_sync(0xffffffffu, s2, o);
                g2 += __shfl_xor_sync(0xffffffffu, g2, o);
            }
            const float sc1 = (1.f / (1.f + __expf(-g1 / s1))) / s1;
            const float sc2 = (1.f / (1.f + __expf(-g2 / s2))) / s2;
            const int r1 = 16 * w + (lane >> 2), r2 = r1 + 8;
            const uint32_t o1b = (uint32_t)(r1 * 128), sw1 = (uint32_t)((r1 & 7) << 4);
            const uint32_t o2b = (uint32_t)(r2 * 128), sw2 = (uint32_t)((r2 & 7) << 4);
            const int cb = (lane & 3) * 4;
#pragma unroll
            for (int nt = 0; nt < 32; nt++) {
                const int ch = nt >> 3;
                const uint32_t colb = (uint32_t)((nt & 7) * 16 + cb);
                // row r1
                float v0 = acc[nt][0] * sc1, v1 = acc[nt][1] * sc1;
                uint32_t hu = pack_bf(v0, v1);
                float h0 = __uint_as_float(hu << 16);
                float h1 = __uint_as_float(hu & 0xffff0000u);
                uint32_t lu = pack_bf(v0 - h0, v1 - h1);
                uint32_t off = (uint32_t)(ch * 16384) + o1b + (colb ^ sw1);
                *(uint32_t*)(smd + PH + off) = hu;
                *(uint32_t*)(smd + PL + off) = lu;
                // row r2
                v0 = acc[nt][2] * sc2; v1 = acc[nt][3] * sc2;
                hu = pack_bf(v0, v1);
                h0 = __uint_as_float(hu << 16);
                h1 = __uint_as_float(hu & 0xffff0000u);
                lu = pack_bf(v0 - h0, v1 - h1);
                off = (uint32_t)(ch * 16384) + o2b + (colb ^ sw2);
                *(uint32_t*)(smd + PH + off) = hu;
                *(uint32_t*)(smd + PL + off) = lu;
            }
        }
        __syncthreads();   // P visible to all warps

        // ============ GEMM2: att[256c x 128j] = tf . P^T  (gated) ============
        float acc2[2][16][4];
#pragma unroll
        for (int m = 0; m < 2; m++)
#pragma unroll
            for (int n = 0; n < 16; n++)
#pragma unroll
                for (int x = 0; x < 4; x++) acc2[m][n][x] = 0.f;

#pragma unroll 1
        for (int kc = 0; kc < 4; kc++) {
            if (kc > 0) __syncthreads();
            {   // stage A: tf rows 0..255 (c), i-chunk kc
                const size_t o = (size_t)qb * 65536 + (size_t)t * 256 + kc * 64;
                stage_row128((const uint4*)(g_tf_h + o), smd + SB_H, t);
                stage_row128((const uint4*)(g_tf_l + o), smd + SB_L, t);
            }
            __syncthreads();
#pragma unroll
            for (int k16 = 0; k16 < 4; k16++) {
                uint32_t ah2[2][4], al2[2][4];
#pragma unroll
                for (int mt = 0; mt < 2; mt++) {
                    const int ar = 32 * w + mt * 16 + a_row_off;
                    const uint32_t ad = sb + SB_H + ar * 128 +
                        ((uint32_t)(k16 * 32 + a_col_off) ^ ((ar & 7) << 4));
                    ldm_x4(ah2[mt][0], ah2[mt][1], ah2[mt][2], ah2[mt][3], ad);
                    ldm_x4(al2[mt][0], al2[mt][1], al2[mt][2], al2[mt][3], ad + 32768);
                }
                const uint32_t bc = (uint32_t)(k16 * 32 + b_col_off);
#pragma unroll
                for (int np = 0; np < 8; np++) {
                    const int br = np * 16 + b_row_off;
                    const uint32_t bd = sb + PH + kc * 16384 + br * 128 +
                                        (bc ^ ((br & 7) << 4));
                    uint32_t bh[4], bl[4];
                    ldm_x4(bh[0], bh[1], bh[2], bh[3], bd);
                    ldm_x4(bl[0], bl[1], bl[2], bl[3], bd + 65536);
#pragma unroll
                    for (int mt = 0; mt < 2; mt++) {
                        mma16816(acc2[mt][2 * np],     ah2[mt], bh[0], bh[1]);
                        mma16816(acc2[mt][2 * np + 1], ah2[mt], bh[2], bh[3]);
                        mma16816(acc2[mt][2 * np],     ah2[mt], bl[0], bl[1]);
                        mma16816(acc2[mt][2 * np + 1], ah2[mt], bl[2], bl[3]);
                        mma16816(acc2[mt][2 * np],     al2[mt], bh[0], bh[1]);
                        mma16816(acc2[mt][2 * np + 1], al2[mt], bh[2], bh[3]);
                    }
                }
            }
        }

        // ===================== epilogue: RMW accumulate ======================
        {
            float* ob = out + (size_t)pb * 65536 + j0;
            const int r0 = lane >> 2;
            const int cbase = (lane & 3) * 2;
#pragma unroll
            for (int mt = 0; mt < 2; mt++) {
#pragma unroll
                for (int half = 0; half < 2; half++) {
                    const int c = 32 * w + mt * 16 + half * 8 + r0;
                    float* rowp = ob + (size_t)c * 256;
#pragma unroll
                    for (int nt = 0; nt < 16; nt++) {
                        float v0 = acc2[mt][nt][half * 2 + 0];
                        float v1 = acc2[mt][nt][half * 2 + 1];
                        float2* pp = (float2*)(rowp + nt * 8 + cbase);
                        if (q == 0) {
                            *pp = make_float2(v0, v1);
                        } else {
                            float2 o = *pp;
                            o.x += v0; o.y += v1;
                            if (q == P_ - 1) { o.x *= invp; o.y *= invp; }
                            *pp = o;
                        }
                    }
                }
            }
        }
    }
}

// ---------------------------------------------------------------------------
extern "C" void kernel_launch(void* const* d_in, const int* in_sizes, int n_in,
                              void* d_out, int out_size) {
    const float* temp = (const float*)d_in[0];
    const float* We   = (const float*)d_in[1];
    const float* Wg   = (const float*)d_in[2];
    const void*  pn   = (n_in > 3) ? d_in[3] : nullptr;
    float* out = (float*)d_out;

    const int n4 = (PB_ * C_ * N_) / 4;   // 1,048,576 float4 elements

    corr_kernel<<<dim3(16, 64), 256>>>(temp, We);
    split_corr<<<n4 / 256, 256>>>();
    split_tf<<<n4 / 256, 256>>>(temp);
    transpose_split<<<dim3(8, 8, 64), 256>>>(temp);
    wtf_kernel<<<64, 256>>>(temp, Wg);

    cudaFuncSetAttribute(fused_mma, cudaFuncAttributeMaxDynamicSharedMemorySize, SMEM_TOTAL);
    fused_mma<<<128, 256, SMEM_TOTAL>>>(pn, out);
}

// round 8
// speedup vs baseline: 2.2733x; 1.0949x over previous
#include <cuda_runtime.h>
#include <cuda_bf16.h>
#include <cstdint>

#define P_ 16
#define B_ 4
#define C_ 256
#define N_ 256
#define PB_ 64

typedef __nv_bfloat16 bf16;

// ---------------- gmem scratch ----------------
__device__ __align__(16) float g_corr[(size_t)PB_ * N_ * C_];   // corr[pb][j][d]
__device__ __align__(16) bf16  g_corr_h[(size_t)PB_ * N_ * C_];
__device__ __align__(16) bf16  g_corr_l[(size_t)PB_ * N_ * C_];
__device__ __align__(16) bf16  g_tf_h[(size_t)PB_ * C_ * N_];   // temp split [pb][c][i]
__device__ __align__(16) bf16  g_tf_l[(size_t)PB_ * C_ * N_];
__device__ __align__(16) bf16  g_tfT_h[(size_t)PB_ * N_ * C_];  // temp^T split [pb][i][c]
__device__ __align__(16) bf16  g_tfT_l[(size_t)PB_ * N_ * C_];
__device__ __align__(16) float g_wtf[(size_t)PB_ * N_];

// ---------------- helpers ----------------
__device__ __forceinline__ uint32_t smem_u32(const void* p) {
    uint32_t a;
    asm("{ .reg .u64 t; cvta.to.shared.u64 t, %1; cvt.u32.u64 %0, t; }" : "=r"(a) : "l"(p));
    return a;
}
__device__ __forceinline__ void ldm_x4(uint32_t& r0, uint32_t& r1, uint32_t& r2,
                                       uint32_t& r3, uint32_t a) {
    asm volatile("ldmatrix.sync.aligned.m8n8.x4.shared.b16 {%0,%1,%2,%3}, [%4];"
                 : "=r"(r0), "=r"(r1), "=r"(r2), "=r"(r3) : "r"(a));
}
__device__ __forceinline__ void mma16816(float* c, const uint32_t* a,
                                         uint32_t b0, uint32_t b1) {
    asm volatile("mma.sync.aligned.m16n8k16.row.col.f32.bf16.bf16.f32 "
                 "{%0,%1,%2,%3}, {%4,%5,%6,%7}, {%8,%9}, {%0,%1,%2,%3};"
                 : "+f"(c[0]), "+f"(c[1]), "+f"(c[2]), "+f"(c[3])
                 : "r"(a[0]), "r"(a[1]), "r"(a[2]), "r"(a[3]), "r"(b0), "r"(b1));
}
__device__ __forceinline__ uint32_t pack_bf(float lo, float hi) {
    uint32_t r;
    asm("cvt.rn.bf16x2.f32 %0, %1, %2;" : "=r"(r) : "f"(hi), "f"(lo));
    return r;
}
__device__ __forceinline__ uint32_t pack2_bf16(bf16 lo, bf16 hi) {
    return ((uint32_t)__bfloat16_as_ushort(hi) << 16) | (uint32_t)__bfloat16_as_ushort(lo);
}
__device__ __forceinline__ void cpa16(uint32_t d, const void* s) {
    asm volatile("cp.async.cg.shared.global [%0], [%1], 16;" :: "r"(d), "l"(s));
}
__device__ __forceinline__ void cp_commit() {
    asm volatile("cp.async.commit_group;" ::: "memory");
}
__device__ __forceinline__ void cp_wait1() {
    asm volatile("cp.async.wait_group 1;" ::: "memory");
}
__device__ __forceinline__ void cp_wait0() {
    asm volatile("cp.async.wait_group 0;" ::: "memory");
}

__device__ __forceinline__ float inv_patch(const void* p) {
    if (p == nullptr) return 1.f / 16.f;
    int iv = *(const int*)p;
    if (iv >= 1 && iv <= 65536) return 1.f / (float)iv;
    float fv = __int_as_float(iv);
    if (fv >= 0.5f && fv <= 65536.f) return 1.f / fv;
    return 1.f / 16.f;
}

// ---------------------------------------------------------------------------
// Prep kernels (verified in R1/R7)
// ---------------------------------------------------------------------------
__global__ void __launch_bounds__(256) corr_kernel(const float* __restrict__ temp,
                                                   const float* __restrict__ We) {
    __shared__ float sX[16][64];
    __shared__ float sW[64][17];
    const int t = threadIdx.x;
    const int tx = t & 15, ty = t >> 4;
    const int ti = blockIdx.x & 3, td = blockIdx.x >> 2;
    const int pb = blockIdx.y;
    const float* tf = temp + (size_t)pb * C_ * N_;
    const int i0 = ti * 64, d0 = td * 64;

    float acc[4][4];
#pragma unroll
    for (int u = 0; u < 4; u++)
#pragma unroll
        for (int v = 0; v < 4; v++) acc[u][v] = 0.f;

#pragma unroll 1
    for (int kc = 0; kc < 16; kc++) {
        __syncthreads();
#pragma unroll
        for (int r = 0; r < 4; r++) {
            int e = t + r * 256;
            sX[e >> 6][e & 63] = tf[(kc * 16 + (e >> 6)) * N_ + i0 + (e & 63)];
        }
#pragma unroll
        for (int r = 0; r < 4; r++) {
            int e = t + r * 256;
            sW[e >> 4][e & 15] = We[(size_t)(d0 + (e >> 4)) * C_ + kc * 16 + (e & 15)];
        }
        __syncthreads();
#pragma unroll
        for (int cc = 0; cc < 16; cc++) {
            float a[4], bb[4];
#pragma unroll
            for (int u = 0; u < 4; u++) a[u] = sX[cc][tx * 4 + u];
#pragma unroll
            for (int v = 0; v < 4; v++) bb[v] = sW[ty * 4 + v][cc];
#pragma unroll
            for (int u = 0; u < 4; u++)
#pragma unroll
                for (int v = 0; v < 4; v++) acc[u][v] += a[u] * bb[v];
        }
    }
    float* cr = g_corr + (size_t)pb * N_ * C_;
#pragma unroll
    for (int u = 0; u < 4; u++) {
        int i = i0 + tx * 4 + u;
        float4 w4 = make_float4(acc[u][0], acc[u][1], acc[u][2], acc[u][3]);
        *(float4*)&cr[(size_t)i * C_ + d0 + ty * 4] = w4;
    }
}

__device__ __forceinline__ void split4(const float4 x, uint2& uh, uint2& ul) {
    bf16 h0 = __float2bfloat16(x.x), h1 = __float2bfloat16(x.y);
    bf16 h2 = __float2bfloat16(x.z), h3 = __float2bfloat16(x.w);
    bf16 l0 = __float2bfloat16(x.x - __bfloat162float(h0));
    bf16 l1 = __float2bfloat16(x.y - __bfloat162float(h1));
    bf16 l2 = __float2bfloat16(x.z - __bfloat162float(h2));
    bf16 l3 = __float2bfloat16(x.w - __bfloat162float(h3));
    uh = make_uint2(pack2_bf16(h0, h1), pack2_bf16(h2, h3));
    ul = make_uint2(pack2_bf16(l0, l1), pack2_bf16(l2, l3));
}
__global__ void __launch_bounds__(256) split_corr() {
    size_t i = (size_t)blockIdx.x * 256 + threadIdx.x;
    float4 x = ((const float4*)g_corr)[i];
    uint2 uh, ul;
    split4(x, uh, ul);
    ((uint2*)g_corr_h)[i] = uh;
    ((uint2*)g_corr_l)[i] = ul;
}
__global__ void __launch_bounds__(256) split_tf(const float* __restrict__ temp) {
    size_t i = (size_t)blockIdx.x * 256 + threadIdx.x;
    float4 x = ((const float4*)temp)[i];
    uint2 uh, ul;
    split4(x, uh, ul);
    ((uint2*)g_tf_h)[i] = uh;
    ((uint2*)g_tf_l)[i] = ul;
}
__global__ void __launch_bounds__(256) transpose_split(const float* __restrict__ temp) {
    __shared__ float tile[32][33];
    const int pb = blockIdx.z;
    const int i0 = blockIdx.x * 32, c0 = blockIdx.y * 32;
    const int tx = threadIdx.x & 31, ty = threadIdx.x >> 5;
    const float* src = temp + (size_t)pb * C_ * N_;
#pragma unroll
    for (int k = 0; k < 4; k++) {
        int c = c0 + ty + k * 8;
        tile[ty + k * 8][tx] = src[(size_t)c * N_ + i0 + tx];
    }
    __syncthreads();
#pragma unroll
    for (int k = 0; k < 4; k++) {
        int i = i0 + ty + k * 8;
        float x = tile[tx][ty + k * 8];
        size_t o = (size_t)pb * N_ * C_ + (size_t)i * C_ + c0 + tx;
        bf16 hh = __float2bfloat16(x);
        g_tfT_h[o] = hh;
        g_tfT_l[o] = __float2bfloat16(x - __bfloat162float(hh));
    }
}
__global__ void __launch_bounds__(256) wtf_kernel(const float* __restrict__ temp,
                                                  const float* __restrict__ Wg) {
    __shared__ float sWg[256];
    const int pb = blockIdx.x, i = threadIdx.x;
    sWg[i] = Wg[i];
    __syncthreads();
    const float* src = temp + (size_t)pb * C_ * N_;
    float s = 0.f;
#pragma unroll 8
    for (int c = 0; c < 256; c++) s += src[(size_t)c * N_ + i] * sWg[c];
    g_wtf[(size_t)pb * N_ + i] = s;
}

// ---------------------------------------------------------------------------
// Fused kernel. 128 CTAs = 64 pb x 2 j-tiles. 256 threads.
// SMEM: [0, 96K)  two 48K stage buffers. Per buffer: B-part 32K (256 rows x
//        128B, packed [32k hi | 32k lo]), A-part 16K (128 rows x 128B).
//       [96K, 224K)  P packed: 8 i-chunks x (128 rows x 128B [hi|lo])
//       [224K+] sWtf(1K) sSum(1K) sG(1K)   -> total exactly 232448 B
// ---------------------------------------------------------------------------
#define STGB 49152
#define PBASE 98304
#define SWTF 229376
#define SSUM 230400
#define SGG  231424
#define SMEM_TOTAL 232448

__device__ __forceinline__ void issue_g1(uint32_t sb, int buf, int t,
                                         int qb, int pb, int j0, int kc) {
    const size_t bo = (size_t)qb * 65536 + (size_t)t * 256 + (size_t)kc * 32;
    const uint32_t dst = sb + buf * STGB + t * 128;
    const uint32_t sw = (uint32_t)((t & 7) << 4);
#pragma unroll
    for (int v = 0; v < 4; v++)
        cpa16(dst + (((uint32_t)(v * 16)) ^ sw), g_tfT_h + bo + v * 8);
#pragma unroll
    for (int v = 0; v < 4; v++)
        cpa16(dst + (((uint32_t)(64 + v * 16)) ^ sw), g_tfT_l + bo + v * 8);
    const int r = t & 127, part = t >> 7;
    const bf16* srcA = (part ? g_corr_l : g_corr_h) +
                       ((size_t)pb * 65536 + (size_t)(j0 + r) * 256 + (size_t)kc * 32);
    const uint32_t dstA = sb + buf * STGB + 32768 + r * 128;
    const uint32_t swA = (uint32_t)((r & 7) << 4);
#pragma unroll
    for (int v = 0; v < 4; v++)
        cpa16(dstA + (((uint32_t)(part * 64 + v * 16)) ^ swA), srcA + v * 8);
}

__device__ __forceinline__ void issue_g2(uint32_t sb, int buf, int t, int qb, int kc) {
    const size_t o = (size_t)qb * 65536 + (size_t)t * 256 + (size_t)kc * 32;
    const uint32_t dst = sb + buf * STGB + t * 128;
    const uint32_t sw = (uint32_t)((t & 7) << 4);
#pragma unroll
    for (int v = 0; v < 4; v++)
        cpa16(dst + (((uint32_t)(v * 16)) ^ sw), g_tf_h + o + v * 8);
#pragma unroll
    for (int v = 0; v < 4; v++)
        cpa16(dst + (((uint32_t)(64 + v * 16)) ^ sw), g_tf_l + o + v * 8);
}

__global__ void __launch_bounds__(256, 1)
fused_mma(const void* __restrict__ pnp, float* __restrict__ out) {
    extern __shared__ char smd[];
    const uint32_t sb = smem_u32(smd);
    float* sWtf = (float*)(smd + SWTF);
    float* sSum = (float*)(smd + SSUM);
    float* sG   = (float*)(smd + SGG);

    const int t = threadIdx.x;
    const int w = t >> 5, lane = t & 31;
    const int jt = blockIdx.x & 1;
    const int pb = blockIdx.x >> 1;
    const int b = pb & 3;
    const int j0 = jt * 128;

    const int wj = w >> 1, wi = w & 1;      // GEMM1: 4 j-warps x 2 i-warps
    const int wc = w >> 1, wj2 = w & 1;     // GEMM2: 4 c-warps x 2 j-warps
    const float invp = inv_patch(pnp);

    const int a_row_off = ((lane >> 3) & 1) * 8 + (lane & 7);
    const int a_col_off = ((lane >> 4) & 1) * 16;
    const int b_row_off = ((lane >> 4) & 1) * 8 + (lane & 7);
    const int b_col_off = ((lane >> 3) & 1) * 16;

    // prologue: q=0 GEMM1 chunk 0
    issue_g1(sb, 0, t, 0 * B_ + b, pb, j0, 0);
    cp_commit();

#pragma unroll 1
    for (int q = 0; q < P_; q++) {
        const int qb = q * B_ + b;
        sWtf[t] = g_wtf[(size_t)qb * N_ + t];

        // ==================== GEMM1: logits[128j x 256i] =====================
        float acc1[2][16][4];
#pragma unroll
        for (int m = 0; m < 2; m++)
#pragma unroll
            for (int n = 0; n < 16; n++)
#pragma unroll
                for (int x = 0; x < 4; x++) acc1[m][n][x] = 0.f;

#pragma unroll 1
        for (int kc = 0; kc < 8; kc++) {
            if (kc < 7) { issue_g1(sb, (kc + 1) & 1, t, qb, pb, j0, kc + 1); cp_commit(); }
            if (kc < 7) cp_wait1(); else cp_wait0();
            __syncthreads();
            const uint32_t bB = sb + (kc & 1) * STGB;
            const uint32_t bA = bB + 32768;
#pragma unroll
            for (int s = 0; s < 2; s++) {
                uint32_t ah[2][4], al[2][4];
#pragma unroll
                for (int mt = 0; mt < 2; mt++) {
                    const int ar = 32 * wj + 16 * mt + a_row_off;
                    const uint32_t sw = (uint32_t)((ar & 7) << 4);
                    const uint32_t ad = bA + ar * 128;
                    ldm_x4(ah[mt][0], ah[mt][1], ah[mt][2], ah[mt][3],
                           ad + (((uint32_t)(s * 32 + a_col_off)) ^ sw));
                    ldm_x4(al[mt][0], al[mt][1], al[mt][2], al[mt][3],
                           ad + (((uint32_t)(64 + s * 32 + a_col_off)) ^ sw));
                }
#pragma unroll
                for (int np = 0; np < 8; np++) {
                    const int br = 128 * wi + np * 16 + b_row_off;
                    const uint32_t sw = (uint32_t)((br & 7) << 4);
                    const uint32_t bd = bB + br * 128;
                    uint32_t bh[4], bl[4];
                    ldm_x4(bh[0], bh[1], bh[2], bh[3],
                           bd + (((uint32_t)(s * 32 + b_col_off)) ^ sw));
                    ldm_x4(bl[0], bl[1], bl[2], bl[3],
                           bd + (((uint32_t)(64 + s * 32 + b_col_off)) ^ sw));
#pragma unroll
                    for (int mt = 0; mt < 2; mt++) {
                        mma16816(acc1[mt][2 * np],     ah[mt], bh[0], bh[1]);
                        mma16816(acc1[mt][2 * np + 1], ah[mt], bh[2], bh[3]);
                        mma16816(acc1[mt][2 * np],     ah[mt], bl[0], bl[1]);
                        mma16816(acc1[mt][2 * np + 1], ah[mt], bl[2], bl[3]);
                        mma16816(acc1[mt][2 * np],     al[mt], bh[0], bh[1]);
                        mma16816(acc1[mt][2 * np + 1], al[mt], bh[2], bh[3]);
                    }
                }
            }
            __syncthreads();
        }

        // prefetch GEMM2 chunk 0 (lands during softmax)
        issue_g2(sb, 0, t, qb, 0);
        cp_commit();

        // ============ softmax (unnorm, shift 40) + gate fold ================
        {
#pragma unroll
            for (int mt = 0; mt < 2; mt++) {
                float s1 = 0.f, g1 = 0.f, s2 = 0.f, g2 = 0.f;
#pragma unroll
                for (int nt = 0; nt < 16; nt++) {
                    const int col = 128 * wi + nt * 8 + (lane & 3) * 2;
                    float2 wv = *(float2*)&sWtf[col];
                    float e0 = __expf(acc1[mt][nt][0] - 40.f);
                    float e1 = __expf(acc1[mt][nt][1] - 40.f);
                    float e2 = __expf(acc1[mt][nt][2] - 40.f);
                    float e3 = __expf(acc1[mt][nt][3] - 40.f);
                    acc1[mt][nt][0] = e0; acc1[mt][nt][1] = e1;
                    acc1[mt][nt][2] = e2; acc1[mt][nt][3] = e3;
                    s1 += e0 + e1; g1 += e0 * wv.x + e1 * wv.y;
                    s2 += e2 + e3; g2 += e2 * wv.x + e3 * wv.y;
                }
#pragma unroll
                for (int o = 1; o <= 2; o <<= 1) {
                    s1 += __shfl_xor_sync(0xffffffffu, s1, o);
                    g1 += __shfl_xor_sync(0xffffffffu, g1, o);
                    s2 += __shfl_xor_sync(0xffffffffu, s2, o);
                    g2 += __shfl_xor_sync(0xffffffffu, g2, o);
                }
                if ((lane & 3) == 0) {
                    const int r1 = 32 * wj + 16 * mt + (lane >> 2);
                    sSum[wi * 128 + r1] = s1;     sG[wi * 128 + r1] = g1;
                    sSum[wi * 128 + r1 + 8] = s2; sG[wi * 128 + r1 + 8] = g2;
                }
            }
            __syncthreads();
            float sc[2][2];
#pragma unroll
            for (int mt = 0; mt < 2; mt++)
#pragma unroll
                for (int h = 0; h < 2; h++) {
                    const int r = 32 * wj + 16 * mt + (lane >> 2) + 8 * h;
                    const float tot = sSum[r] + sSum[128 + r];
                    const float gt  = sG[r] + sG[128 + r];
                    sc[mt][h] = (1.f / (1.f + __expf(-gt / tot))) / tot;
                }
            // write P (packed [hi|lo] rows)
#pragma unroll
            for (int mt = 0; mt < 2; mt++) {
                const int r1 = 32 * wj + 16 * mt + (lane >> 2);
                const int r2 = r1 + 8;
                const uint32_t sw1 = (uint32_t)((r1 & 7) << 4);
                const uint32_t sw2 = (uint32_t)((r2 & 7) << 4);
#pragma unroll
                for (int nt = 0; nt < 16; nt++) {
                    const int ch = 4 * wi + (nt >> 2);
                    const uint32_t off = (uint32_t)((nt & 3) * 16 + (lane & 3) * 4);
                    char* base = smd + PBASE + ch * 16384;
                    // row r1 (x0, x1)
                    float v0 = acc1[mt][nt][0] * sc[mt][0];
                    float v1 = acc1[mt][nt][1] * sc[mt][0];
                    uint32_t hu = pack_bf(v0, v1);
                    float h0 = __uint_as_float(hu << 16);
                    float h1 = __uint_as_float(hu & 0xffff0000u);
                    uint32_t lu = pack_bf(v0 - h0, v1 - h1);
                    *(uint32_t*)(base + r1 * 128 + (off ^ sw1)) = hu;
                    *(uint32_t*)(base + r1 * 128 + ((64 + off) ^ sw1)) = lu;
                    // row r2 (x2, x3)
                    v0 = acc1[mt][nt][2] * sc[mt][1];
                    v1 = acc1[mt][nt][3] * sc[mt][1];
                    hu = pack_bf(v0, v1);
                    h0 = __uint_as_float(hu << 16);
                    h1 = __uint_as_float(hu & 0xffff0000u);
                    lu = pack_bf(v0 - h0, v1 - h1);
                    *(uint32_t*)(base + r2 * 128 + (off ^ sw2)) = hu;
                    *(uint32_t*)(base + r2 * 128 + ((64 + off) ^ sw2)) = lu;
                }
            }
        }

        // ============ GEMM2: att[256c x 128j] = tf . P^T (gated) =============
        float acc2[4][8][4];
#pragma unroll
        for (int m = 0; m < 4; m++)
#pragma unroll
            for (int n = 0; n < 8; n++)
#pragma unroll
                for (int x = 0; x < 4; x++) acc2[m][n][x] = 0.f;

#pragma unroll 1
        for (int kc = 0; kc < 8; kc++) {
            if (kc < 7) { issue_g2(sb, (kc + 1) & 1, t, qb, kc + 1); cp_commit(); }
            if (kc < 7) cp_wait1(); else cp_wait0();
            __syncthreads();
            const uint32_t bA2 = sb + (kc & 1) * STGB;
            const uint32_t pB = sb + PBASE + kc * 16384;
#pragma unroll
            for (int s = 0; s < 2; s++) {
#pragma unroll
                for (int mp = 0; mp < 2; mp++) {   // mt pairs {0,1}, {2,3}
                    uint32_t ah[2][4], al[2][4];
#pragma unroll
                    for (int mi = 0; mi < 2; mi++) {
                        const int ar = 64 * wc + 16 * (2 * mp + mi) + a_row_off;
                        const uint32_t sw = (uint32_t)((ar & 7) << 4);
                        const uint32_t ad = bA2 + ar * 128;
                        ldm_x4(ah[mi][0], ah[mi][1], ah[mi][2], ah[mi][3],
                               ad + (((uint32_t)(s * 32 + a_col_off)) ^ sw));
                        ldm_x4(al[mi][0], al[mi][1], al[mi][2], al[mi][3],
                               ad + (((uint32_t)(64 + s * 32 + a_col_off)) ^ sw));
                    }
#pragma unroll
                    for (int np = 0; np < 4; np++) {
                        const int br = 64 * wj2 + np * 16 + b_row_off;
                        const uint32_t sw = (uint32_t)((br & 7) << 4);
                        const uint32_t bd = pB + br * 128;
                        uint32_t bh[4], bl[4];
                        ldm_x4(bh[0], bh[1], bh[2], bh[3],
                               bd + (((uint32_t)(s * 32 + b_col_off)) ^ sw));
                        ldm_x4(bl[0], bl[1], bl[2], bl[3],
                               bd + (((uint32_t)(64 + s * 32 + b_col_off)) ^ sw));
#pragma unroll
                        for (int mi = 0; mi < 2; mi++) {
                            float* ce = acc2[2 * mp + mi][2 * np];
                            float* co = acc2[2 * mp + mi][2 * np + 1];
                            mma16816(ce, ah[mi], bh[0], bh[1]);
                            mma16816(co, ah[mi], bh[2], bh[3]);
                            mma16816(ce, ah[mi], bl[0], bl[1]);
                            mma16816(co, ah[mi], bl[2], bl[3]);
                            mma16816(ce, al[mi], bh[0], bh[1]);
                            mma16816(co, al[mi], bh[2], bh[3]);
                        }
                    }
                }
            }
            __syncthreads();
        }

        // prefetch next q's GEMM1 chunk 0 (lands during epilogue)
        if (q < P_ - 1) { issue_g1(sb, 0, t, qb + B_, pb, j0, 0); cp_commit(); }

        // ===================== epilogue: RMW accumulate ======================
        {
            float* ob = out + (size_t)pb * 65536 + j0 + 64 * wj2;
#pragma unroll
            for (int mt = 0; mt < 4; mt++) {
#pragma unroll
                for (int h = 0; h < 2; h++) {
                    const int c = 64 * wc + 16 * mt + 8 * h + (lane >> 2);
                    float* rowp = ob + (size_t)c * 256;
#pragma unroll
                    for (int nt = 0; nt < 8; nt++) {
                        float v0 = acc2[mt][nt][2 * h];
                        float v1 = acc2[mt][nt][2 * h + 1];
                        float2* pp = (float2*)(rowp + nt * 8 + (lane & 3) * 2);
                        if (q == 0) {
                            *pp = make_float2(v0, v1);
                        } else {
                            float2 o = *pp;
                            o.x += v0; o.y += v1;
                            if (q == P_ - 1) { o.x *= invp; o.y *= invp; }
                            *pp = o;
                        }
                    }
                }
            }
        }
    }
}

// ---------------------------------------------------------------------------
extern "C" void kernel_launch(void* const* d_in, const int* in_sizes, int n_in,
                              void* d_out, int out_size) {
    const float* temp = (const float*)d_in[0];
    const float* We   = (const float*)d_in[1];
    const float* Wg   = (const float*)d_in[2];
    const void*  pn   = (n_in > 3) ? d_in[3] : nullptr;
    float* out = (float*)d_out;

    const int n4 = (PB_ * C_ * N_) / 4;

    corr_kernel<<<dim3(16, 64), 256>>>(temp, We);
    split_corr<<<n4 / 256, 256>>>();
    split_tf<<<n4 / 256, 256>>>(temp);
    transpose_split<<<dim3(8, 8, 64), 256>>>(temp);
    wtf_kernel<<<64, 256>>>(temp, Wg);

    cudaFuncSetAttribute(fused_mma, cudaFuncAttributeMaxDynamicSharedMemorySize, SMEM_TOTAL);
    fused_mma<<<128, 256, SMEM_TOTAL>>>(pn, out);
}

// round 9
// speedup vs baseline: 2.9922x; 1.3162x over previous
#include <cuda_runtime.h>
#include <cuda_bf16.h>
#include <cstdint>

#define P_ 16
#define B_ 4
#define C_ 256
#define N_ 256
#define PB_ 64

typedef __nv_bfloat16 bf16;

// ---------------- gmem scratch ----------------
__device__ __align__(16) float g_corr[(size_t)PB_ * N_ * C_];   // corr[pb][j][d]
__device__ __align__(16) bf16  g_corr_h[(size_t)PB_ * N_ * C_];
__device__ __align__(16) bf16  g_corr_l[(size_t)PB_ * N_ * C_];
__device__ __align__(16) unsigned short g_tf_f16[(size_t)PB_ * C_ * N_];  // temp fp16 [pb][c][i]
__device__ __align__(16) bf16  g_tfT_h[(size_t)PB_ * N_ * C_];  // temp^T split [pb][i][c]
__device__ __align__(16) bf16  g_tfT_l[(size_t)PB_ * N_ * C_];
__device__ __align__(16) float g_wtf[(size_t)PB_ * N_];

// ---------------- helpers ----------------
__device__ __forceinline__ uint32_t smem_u32(const void* p) {
    uint32_t a;
    asm("{ .reg .u64 t; cvta.to.shared.u64 t, %1; cvt.u32.u64 %0, t; }" : "=r"(a) : "l"(p));
    return a;
}
__device__ __forceinline__ void ldm_x4(uint32_t& r0, uint32_t& r1, uint32_t& r2,
                                       uint32_t& r3, uint32_t a) {
    asm volatile("ldmatrix.sync.aligned.m8n8.x4.shared.b16 {%0,%1,%2,%3}, [%4];"
                 : "=r"(r0), "=r"(r1), "=r"(r2), "=r"(r3) : "r"(a));
}
__device__ __forceinline__ void mma16816(float* c, const uint32_t* a,
                                         uint32_t b0, uint32_t b1) {
    asm volatile("mma.sync.aligned.m16n8k16.row.col.f32.bf16.bf16.f32 "
                 "{%0,%1,%2,%3}, {%4,%5,%6,%7}, {%8,%9}, {%0,%1,%2,%3};"
                 : "+f"(c[0]), "+f"(c[1]), "+f"(c[2]), "+f"(c[3])
                 : "r"(a[0]), "r"(a[1]), "r"(a[2]), "r"(a[3]), "r"(b0), "r"(b1));
}
__device__ __forceinline__ void mma16816h(float* c, const uint32_t* a,
                                          uint32_t b0, uint32_t b1) {
    asm volatile("mma.sync.aligned.m16n8k16.row.col.f32.f16.f16.f32 "
                 "{%0,%1,%2,%3}, {%4,%5,%6,%7}, {%8,%9}, {%0,%1,%2,%3};"
                 : "+f"(c[0]), "+f"(c[1]), "+f"(c[2]), "+f"(c[3])
                 : "r"(a[0]), "r"(a[1]), "r"(a[2]), "r"(a[3]), "r"(b0), "r"(b1));
}
__device__ __forceinline__ uint32_t pack_f16(float lo, float hi) {
    uint32_t r;
    asm("cvt.rn.f16x2.f32 %0, %1, %2;" : "=r"(r) : "f"(hi), "f"(lo));
    return r;
}
__device__ __forceinline__ uint32_t pack2_bf16(bf16 lo, bf16 hi) {
    return ((uint32_t)__bfloat16_as_ushort(hi) << 16) | (uint32_t)__bfloat16_as_ushort(lo);
}
__device__ __forceinline__ void cpa16(uint32_t d, const void* s) {
    asm volatile("cp.async.cg.shared.global [%0], [%1], 16;" :: "r"(d), "l"(s));
}
__device__ __forceinline__ void cp_commit() {
    asm volatile("cp.async.commit_group;" ::: "memory");
}
__device__ __forceinline__ void cp_wait1() {
    asm volatile("cp.async.wait_group 1;" ::: "memory");
}
__device__ __forceinline__ void cp_wait0() {
    asm volatile("cp.async.wait_group 0;" ::: "memory");
}

__device__ __forceinline__ float inv_patch(const void* p) {
    if (p == nullptr) return 1.f / 16.f;
    int iv = *(const int*)p;
    if (iv >= 1 && iv <= 65536) return 1.f / (float)iv;
    float fv = __int_as_float(iv);
    if (fv >= 0.5f && fv <= 65536.f) return 1.f / fv;
    return 1.f / 16.f;
}

// ---------------------------------------------------------------------------
// Prep kernels
// ---------------------------------------------------------------------------
__global__ void __launch_bounds__(256) corr_kernel(const float* __restrict__ temp,
                                                   const float* __restrict__ We) {
    __shared__ float sX[16][64];
    __shared__ float sW[64][17];
    const int t = threadIdx.x;
    const int tx = t & 15, ty = t >> 4;
    const int ti = blockIdx.x & 3, td = blockIdx.x >> 2;
    const int pb = blockIdx.y;
    const float* tf = temp + (size_t)pb * C_ * N_;
    const int i0 = ti * 64, d0 = td * 64;

    float acc[4][4];
#pragma unroll
    for (int u = 0; u < 4; u++)
#pragma unroll
        for (int v = 0; v < 4; v++) acc[u][v] = 0.f;

#pragma unroll 1
    for (int kc = 0; kc < 16; kc++) {
        __syncthreads();
#pragma unroll
        for (int r = 0; r < 4; r++) {
            int e = t + r * 256;
            sX[e >> 6][e & 63] = tf[(kc * 16 + (e >> 6)) * N_ + i0 + (e & 63)];
        }
#pragma unroll
        for (int r = 0; r < 4; r++) {
            int e = t + r * 256;
            sW[e >> 4][e & 15] = We[(size_t)(d0 + (e >> 4)) * C_ + kc * 16 + (e & 15)];
        }
        __syncthreads();
#pragma unroll
        for (int cc = 0; cc < 16; cc++) {
            float a[4], bb[4];
#pragma unroll
            for (int u = 0; u < 4; u++) a[u] = sX[cc][tx * 4 + u];
#pragma unroll
            for (int v = 0; v < 4; v++) bb[v] = sW[ty * 4 + v][cc];
#pragma unroll
            for (int u = 0; u < 4; u++)
#pragma unroll
                for (int v = 0; v < 4; v++) acc[u][v] += a[u] * bb[v];
        }
    }
    float* cr = g_corr + (size_t)pb * N_ * C_;
#pragma unroll
    for (int u = 0; u < 4; u++) {
        int i = i0 + tx * 4 + u;
        float4 w4 = make_float4(acc[u][0], acc[u][1], acc[u][2], acc[u][3]);
        *(float4*)&cr[(size_t)i * C_ + d0 + ty * 4] = w4;
    }
}

__device__ __forceinline__ void split4(const float4 x, uint2& uh, uint2& ul) {
    bf16 h0 = __float2bfloat16(x.x), h1 = __float2bfloat16(x.y);
    bf16 h2 = __float2bfloat16(x.z), h3 = __float2bfloat16(x.w);
    bf16 l0 = __float2bfloat16(x.x - __bfloat162float(h0));
    bf16 l1 = __float2bfloat16(x.y - __bfloat162float(h1));
    bf16 l2 = __float2bfloat16(x.z - __bfloat162float(h2));
    bf16 l3 = __float2bfloat16(x.w - __bfloat162float(h3));
    uh = make_uint2(pack2_bf16(h0, h1), pack2_bf16(h2, h3));
    ul = make_uint2(pack2_bf16(l0, l1), pack2_bf16(l2, l3));
}
__global__ void __launch_bounds__(256) split_corr() {
    size_t i = (size_t)blockIdx.x * 256 + threadIdx.x;
    float4 x = ((const float4*)g_corr)[i];
    uint2 uh, ul;
    split4(x, uh, ul);
    ((uint2*)g_corr_h)[i] = uh;
    ((uint2*)g_corr_l)[i] = ul;
}
__global__ void __launch_bounds__(256) cvt_tf_f16(const float* __restrict__ temp) {
    size_t i = (size_t)blockIdx.x * 256 + threadIdx.x;
    float4 x = ((const float4*)temp)[i];
    uint32_t a = pack_f16(x.x, x.y);
    uint32_t b = pack_f16(x.z, x.w);
    ((uint2*)g_tf_f16)[i] = make_uint2(a, b);
}
__global__ void __launch_bounds__(256) transpose_split(const float* __restrict__ temp) {
    __shared__ float tile[32][33];
    const int pb = blockIdx.z;
    const int i0 = blockIdx.x * 32, c0 = blockIdx.y * 32;
    const int tx = threadIdx.x & 31, ty = threadIdx.x >> 5;
    const float* src = temp + (size_t)pb * C_ * N_;
#pragma unroll
    for (int k = 0; k < 4; k++) {
        int c = c0 + ty + k * 8;
        tile[ty + k * 8][tx] = src[(size_t)c * N_ + i0 + tx];
    }
    __syncthreads();
#pragma unroll
    for (int k = 0; k < 4; k++) {
        int i = i0 + ty + k * 8;
        float x = tile[tx][ty + k * 8];
        size_t o = (size_t)pb * N_ * C_ + (size_t)i * C_ + c0 + tx;
        bf16 hh = __float2bfloat16(x);
        g_tfT_h[o] = hh;
        g_tfT_l[o] = __float2bfloat16(x - __bfloat162float(hh));
    }
}
__global__ void __launch_bounds__(256) wtf_kernel(const float* __restrict__ temp,
                                                  const float* __restrict__ Wg) {
    __shared__ float sWg[256];
    const int pb = blockIdx.x, i = threadIdx.x;
    sWg[i] = Wg[i];
    __syncthreads();
    const float* src = temp + (size_t)pb * C_ * N_;
    float s = 0.f;
#pragma unroll 8
    for (int c = 0; c < 256; c++) s += src[(size_t)c * N_ + i] * sWg[c];
    g_wtf[(size_t)pb * N_ + i] = s;
}

// ---------------------------------------------------------------------------
// Fused kernel. 128 CTAs = 64 pb x 2 j-tiles. 256 threads.
// SMEM:
//   [0,96K)     GEMM1: two 48K stage buffers (B 32K [hi|lo rows], A 16K)
//   [0,64K)     GEMM2 (temporal alias): two 32K tf-fp16 stage buffers
//   [96K,160K)  P fp16: 4 i-chunks x (128 rows x 128B)
//   [160K+]     sWtf(1K) sSum(1K) sG(1K)
// ---------------------------------------------------------------------------
#define STGB 49152
#define G2B  32768
#define PBASE 98304
#define SWTF 163840
#define SSUM 164864
#define SGG  165888
#define SMEM_TOTAL 166912

__device__ __forceinline__ void issue_g1(uint32_t sb, int buf, int t,
                                         int qb, int pb, int j0, int kc) {
    const size_t bo = (size_t)qb * 65536 + (size_t)t * 256 + (size_t)kc * 32;
    const uint32_t dst = sb + buf * STGB + t * 128;
    const uint32_t sw = (uint32_t)((t & 7) << 4);
#pragma unroll
    for (int v = 0; v < 4; v++)
        cpa16(dst + (((uint32_t)(v * 16)) ^ sw), g_tfT_h + bo + v * 8);
#pragma unroll
    for (int v = 0; v < 4; v++)
        cpa16(dst + (((uint32_t)(64 + v * 16)) ^ sw), g_tfT_l + bo + v * 8);
    const int r = t & 127, part = t >> 7;
    const bf16* srcA = (part ? g_corr_l : g_corr_h) +
                       ((size_t)pb * 65536 + (size_t)(j0 + r) * 256 + (size_t)kc * 32);
    const uint32_t dstA = sb + buf * STGB + 32768 + r * 128;
    const uint32_t swA = (uint32_t)((r & 7) << 4);
#pragma unroll
    for (int v = 0; v < 4; v++)
        cpa16(dstA + (((uint32_t)(part * 64 + v * 16)) ^ swA), srcA + v * 8);
}

// GEMM2: stage tf fp16 chunk kc (64 i-values = 128B per c-row)
__device__ __forceinline__ void issue_g2(uint32_t sb, int buf, int t, int qb, int kc) {
    const unsigned short* src = g_tf_f16 + (size_t)qb * 65536 + (size_t)t * 256 + (size_t)kc * 64;
    const uint32_t dst = sb + buf * G2B + t * 128;
    const uint32_t sw = (uint32_t)((t & 7) << 4);
#pragma unroll
    for (int v = 0; v < 8; v++)
        cpa16(dst + (((uint32_t)(v * 16)) ^ sw), src + v * 8);
}

__global__ void __launch_bounds__(256, 1)
fused_mma(const void* __restrict__ pnp, float* __restrict__ out) {
    extern __shared__ char smd[];
    const uint32_t sb = smem_u32(smd);
    float* sWtf = (float*)(smd + SWTF);
    float* sSum = (float*)(smd + SSUM);
    float* sG   = (float*)(smd + SGG);

    const int t = threadIdx.x;
    const int w = t >> 5, lane = t & 31;
    const int jt = blockIdx.x & 1;
    const int pb = blockIdx.x >> 1;
    const int b = pb & 3;
    const int j0 = jt * 128;

    const int wj = w >> 1, wi = w & 1;      // GEMM1: 4 j-warps x 2 i-warps
    const int wc = w >> 1, wj2 = w & 1;     // GEMM2: 4 c-warps x 2 j-warps
    const float invp = inv_patch(pnp);

    const int a_row_off = ((lane >> 3) & 1) * 8 + (lane & 7);
    const int a_col_off = ((lane >> 4) & 1) * 16;
    const int b_row_off = ((lane >> 4) & 1) * 8 + (lane & 7);
    const int b_col_off = ((lane >> 3) & 1) * 16;

    // prologue: q=0 GEMM1 chunk 0
    issue_g1(sb, 0, t, 0 * B_ + b, pb, j0, 0);
    cp_commit();

#pragma unroll 1
    for (int q = 0; q < P_; q++) {
        const int qb = q * B_ + b;
        sWtf[t] = g_wtf[(size_t)qb * N_ + t];

        // ==================== GEMM1: logits[128j x 256i], bf16 3-term ========
        float acc1[2][16][4];
#pragma unroll
        for (int m = 0; m < 2; m++)
#pragma unroll
            for (int n = 0; n < 16; n++)
#pragma unroll
                for (int x = 0; x < 4; x++) acc1[m][n][x] = 0.f;

#pragma unroll 1
        for (int kc = 0; kc < 8; kc++) {
            if (kc < 7) { issue_g1(sb, (kc + 1) & 1, t, qb, pb, j0, kc + 1); cp_commit(); }
            if (kc < 7) cp_wait1(); else cp_wait0();
            __syncthreads();
            const uint32_t bB = sb + (kc & 1) * STGB;
            const uint32_t bA = bB + 32768;
#pragma unroll
            for (int s = 0; s < 2; s++) {
                uint32_t ah[2][4], al[2][4];
#pragma unroll
                for (int mt = 0; mt < 2; mt++) {
                    const int ar = 32 * wj + 16 * mt + a_row_off;
                    const uint32_t sw = (uint32_t)((ar & 7) << 4);
                    const uint32_t ad = bA + ar * 128;
                    ldm_x4(ah[mt][0], ah[mt][1], ah[mt][2], ah[mt][3],
                           ad + (((uint32_t)(s * 32 + a_col_off)) ^ sw));
                    ldm_x4(al[mt][0], al[mt][1], al[mt][2], al[mt][3],
                           ad + (((uint32_t)(64 + s * 32 + a_col_off)) ^ sw));
                }
#pragma unroll
                for (int np = 0; np < 8; np++) {
                    const int br = 128 * wi + np * 16 + b_row_off;
                    const uint32_t sw = (uint32_t)((br & 7) << 4);
                    const uint32_t bd = bB + br * 128;
                    uint32_t bh[4], bl[4];
                    ldm_x4(bh[0], bh[1], bh[2], bh[3],
                           bd + (((uint32_t)(s * 32 + b_col_off)) ^ sw));
                    ldm_x4(bl[0], bl[1], bl[2], bl[3],
                           bd + (((uint32_t)(64 + s * 32 + b_col_off)) ^ sw));
#pragma unroll
                    for (int mt = 0; mt < 2; mt++) {
                        mma16816(acc1[mt][2 * np],     ah[mt], bh[0], bh[1]);
                        mma16816(acc1[mt][2 * np + 1], ah[mt], bh[2], bh[3]);
                        mma16816(acc1[mt][2 * np],     ah[mt], bl[0], bl[1]);
                        mma16816(acc1[mt][2 * np + 1], ah[mt], bl[2], bl[3]);
                        mma16816(acc1[mt][2 * np],     al[mt], bh[0], bh[1]);
                        mma16816(acc1[mt][2 * np + 1], al[mt], bh[2], bh[3]);
                    }
                }
            }
            __syncthreads();
        }

        // prefetch GEMM2 chunk 0 (lands during softmax); GEMM1 buf0 is free
        issue_g2(sb, 0, t, qb, 0);
        cp_commit();

        // ============ softmax (unnorm, shift 40) + gate fold + P fp16 =======
        {
#pragma unroll
            for (int mt = 0; mt < 2; mt++) {
                float s1 = 0.f, g1 = 0.f, s2 = 0.f, g2 = 0.f;
#pragma unroll
                for (int nt = 0; nt < 16; nt++) {
                    const int col = 128 * wi + nt * 8 + (lane & 3) * 2;
                    float2 wv = *(float2*)&sWtf[col];
                    float e0 = __expf(acc1[mt][nt][0] - 40.f);
                    float e1 = __expf(acc1[mt][nt][1] - 40.f);
                    float e2 = __expf(acc1[mt][nt][2] - 40.f);
                    float e3 = __expf(acc1[mt][nt][3] - 40.f);
                    acc1[mt][nt][0] = e0; acc1[mt][nt][1] = e1;
                    acc1[mt][nt][2] = e2; acc1[mt][nt][3] = e3;
                    s1 += e0 + e1; g1 += e0 * wv.x + e1 * wv.y;
                    s2 += e2 + e3; g2 += e2 * wv.x + e3 * wv.y;
                }
#pragma unroll
                for (int o = 1; o <= 2; o <<= 1) {
                    s1 += __shfl_xor_sync(0xffffffffu, s1, o);
                    g1 += __shfl_xor_sync(0xffffffffu, g1, o);
                    s2 += __shfl_xor_sync(0xffffffffu, s2, o);
                    g2 += __shfl_xor_sync(0xffffffffu, g2, o);
                }
                if ((lane & 3) == 0) {
                    const int r1 = 32 * wj + 16 * mt + (lane >> 2);
                    sSum[wi * 128 + r1] = s1;     sG[wi * 128 + r1] = g1;
                    sSum[wi * 128 + r1 + 8] = s2; sG[wi * 128 + r1 + 8] = g2;
                }
            }
            __syncthreads();
            float sc[2][2];
#pragma unroll
            for (int mt = 0; mt < 2; mt++)
#pragma unroll
                for (int h = 0; h < 2; h++) {
                    const int r = 32 * wj + 16 * mt + (lane >> 2) + 8 * h;
                    const float tot = sSum[r] + sSum[128 + r];
                    const float gt  = sG[r] + sG[128 + r];
                    sc[mt][h] = (1.f / (1.f + __expf(-gt / tot))) / tot;
                }
            // write P (single fp16 plane, 4 chunks x 128 rows x 128B)
#pragma unroll
            for (int mt = 0; mt < 2; mt++) {
                const int r1 = 32 * wj + 16 * mt + (lane >> 2);
                const int r2 = r1 + 8;
                const uint32_t sw1 = (uint32_t)((r1 & 7) << 4);
                const uint32_t sw2 = (uint32_t)((r2 & 7) << 4);
#pragma unroll
                for (int nt = 0; nt < 16; nt++) {
                    const int ch = 2 * wi + (nt >> 3);
                    const uint32_t off = (uint32_t)((nt & 7) * 16 + (lane & 3) * 4);
                    char* base = smd + PBASE + ch * 16384;
                    uint32_t hu = pack_f16(acc1[mt][nt][0] * sc[mt][0],
                                           acc1[mt][nt][1] * sc[mt][0]);
                    *(uint32_t*)(base + r1 * 128 + (off ^ sw1)) = hu;
                    hu = pack_f16(acc1[mt][nt][2] * sc[mt][1],
                                  acc1[mt][nt][3] * sc[mt][1]);
                    *(uint32_t*)(base + r2 * 128 + (off ^ sw2)) = hu;
                }
            }
        }

        // ============ GEMM2: att[256c x 128j] = tf_f16 . P^T, 1-term ========
        float acc2[4][8][4];
#pragma unroll
        for (int m = 0; m < 4; m++)
#pragma unroll
            for (int n = 0; n < 8; n++)
#pragma unroll
                for (int x = 0; x < 4; x++) acc2[m][n][x] = 0.f;

#pragma unroll 1
        for (int kc = 0; kc < 4; kc++) {
            if (kc < 3) { issue_g2(sb, (kc + 1) & 1, t, qb, kc + 1); cp_commit(); }
            if (kc < 3) cp_wait1(); else cp_wait0();
            __syncthreads();
            const uint32_t bA2 = sb + (kc & 1) * G2B;
            const uint32_t pB = sb + PBASE + kc * 16384;
#pragma unroll
            for (int s = 0; s < 4; s++) {
                uint32_t ah[4][4];
#pragma unroll
                for (int mt = 0; mt < 4; mt++) {
                    const int ar = 64 * wc + 16 * mt + a_row_off;
                    const uint32_t sw = (uint32_t)((ar & 7) << 4);
                    ldm_x4(ah[mt][0], ah[mt][1], ah[mt][2], ah[mt][3],
                           bA2 + ar * 128 + (((uint32_t)(s * 32 + a_col_off)) ^ sw));
                }
#pragma unroll
                for (int np = 0; np < 4; np++) {
                    const int br = 64 * wj2 + np * 16 + b_row_off;
                    const uint32_t sw = (uint32_t)((br & 7) << 4);
                    uint32_t bh[4];
                    ldm_x4(bh[0], bh[1], bh[2], bh[3],
                           pB + br * 128 + (((uint32_t)(s * 32 + b_col_off)) ^ sw));
#pragma unroll
                    for (int mt = 0; mt < 4; mt++) {
                        mma16816h(acc2[mt][2 * np],     ah[mt], bh[0], bh[1]);
                        mma16816h(acc2[mt][2 * np + 1], ah[mt], bh[2], bh[3]);
                    }
                }
            }
            __syncthreads();
        }

        // prefetch next q's GEMM1 chunk 0 (lands during epilogue)
        if (q < P_ - 1) { issue_g1(sb, 0, t, qb + B_, pb, j0, 0); cp_commit(); }

        // ===================== epilogue: RMW accumulate ======================
        {
            float* ob = out + (size_t)pb * 65536 + j0 + 64 * wj2;
#pragma unroll
            for (int mt = 0; mt < 4; mt++) {
#pragma unroll
                for (int h = 0; h < 2; h++) {
                    const int c = 64 * wc + 16 * mt + 8 * h + (lane >> 2);
                    float* rowp = ob + (size_t)c * 256;
#pragma unroll
                    for (int nt = 0; nt < 8; nt++) {
                        float v0 = acc2[mt][nt][2 * h];
                        float v1 = acc2[mt][nt][2 * h + 1];
                        float2* pp = (float2*)(rowp + nt * 8 + (lane & 3) * 2);
                        if (q == 0) {
                            *pp = make_float2(v0, v1);
                        } else {
                            float2 o = *pp;
                            o.x += v0; o.y += v1;
                            if (q == P_ - 1) { o.x *= invp; o.y *= invp; }
                            *pp = o;
                        }
                    }
                }
            }
        }
    }
}

// ---------------------------------------------------------------------------
extern "C" void kernel_launch(void* const* d_in, const int* in_sizes, int n_in,
                              void* d_out, int out_size) {
    const float* temp = (const float*)d_in[0];
    const float* We   = (const float*)d_in[1];
    const float* Wg   = (const float*)d_in[2];
    const void*  pn   = (n_in > 3) ? d_in[3] : nullptr;
    float* out = (float*)d_out;

    const int n4 = (PB_ * C_ * N_) / 4;

    corr_kernel<<<dim3(16, 64), 256>>>(temp, We);
    split_corr<<<n4 / 256, 256>>>();
    cvt_tf_f16<<<n4 / 256, 256>>>(temp);
    transpose_split<<<dim3(8, 8, 64), 256>>>(temp);
    wtf_kernel<<<64, 256>>>(temp, Wg);

    cudaFuncSetAttribute(fused_mma, cudaFuncAttributeMaxDynamicSharedMemorySize, SMEM_TOTAL);
    fused_mma<<<128, 256, SMEM_TOTAL>>>(pn, out);
}